// round 1
// baseline (speedup 1.0000x reference)
#include <cuda_runtime.h>
#include <cuda_bf16.h>
#include <cstdint>

// Polarisation Thole dipole tensor:
//   inputs (metadata order): species[N](int, unused), edge_src[E](int),
//     edge_dst[E](int), distances[E](f32), vec[E,3](f32), polarisability[N](f32)
//   output: t_matrix[E,3,3] f32
//
// au3   = 0.39 * d^3 / sqrt(p_i * p_j)          (unit conversions cancel)
// l3    = 1 - exp(-au3);  l5 = 1 - (1+au3)exp(-au3)
// T     = BOHR^3 * ( 3*l5 * v v^T / d^5  -  l3 * I / d^3 )

#define BOHR 0.52917721067f
#define A_MUTUAL 0.39f

static constexpr int TPB = 256;

__global__ __launch_bounds__(TPB)
void thole_kernel(const int* __restrict__ edge_src,
                  const int* __restrict__ edge_dst,
                  const float* __restrict__ distances,
                  const float* __restrict__ vec,
                  const float* __restrict__ pol,
                  float* __restrict__ out,
                  int E)
{
    __shared__ __align__(16) float s[TPB * 9];

    const int tid = threadIdx.x;
    const int blockStart = blockIdx.x * TPB;
    const int e = blockStart + tid;

    const float BOHR3 = BOHR * BOHR * BOHR;

    if (e < E) {
        const float d  = distances[e];
        const float vx = vec[3 * e + 0];
        const float vy = vec[3 * e + 1];
        const float vz = vec[3 * e + 2];
        const float pi = pol[edge_src[e]];
        const float pj = pol[edge_dst[e]];

        const float d2 = d * d;
        const float d3 = d2 * d;

        const float au3 = A_MUTUAL * d3 * rsqrtf(pi * pj);
        const float ex  = __expf(-au3);
        const float l3  = 1.0f - ex;
        const float l5  = 1.0f - (1.0f + au3) * ex;

        const float inv_d3 = __frcp_rn(d3);
        const float inv_d5 = inv_d3 * __frcp_rn(d2);

        const float c5 = 3.0f * l5 * inv_d5 * BOHR3;   // outer-product coeff
        const float c3 = l3 * inv_d3 * BOHR3;          // diagonal coeff

        float* t = &s[tid * 9];
        const float c5x = c5 * vx, c5y = c5 * vy, c5z = c5 * vz;
        t[0] = c5x * vx - c3;
        t[1] = c5x * vy;
        t[2] = c5x * vz;
        t[3] = c5y * vx;
        t[4] = c5y * vy - c3;
        t[5] = c5y * vz;
        t[6] = c5z * vx;
        t[7] = c5z * vy;
        t[8] = c5z * vz - c3;
    }
    __syncthreads();

    // Flush shared staging to global, fully coalesced.
    const int nEdges = min(TPB, E - blockStart);        // edges this block owns
    const int nFloats = nEdges * 9;
    float* outBase = out + (size_t)blockStart * 9;

    if (nFloats == TPB * 9) {
        // Full block: vectorized float4 stores (TPB*9/4 = 576 float4s).
        const float4* s4 = reinterpret_cast<const float4*>(s);
        float4* o4 = reinterpret_cast<float4*>(outBase);
        #pragma unroll
        for (int i = tid; i < TPB * 9 / 4; i += TPB)
            o4[i] = s4[i];
    } else {
        for (int i = tid; i < nFloats; i += TPB)
            outBase[i] = s[i];
    }
}

extern "C" void kernel_launch(void* const* d_in, const int* in_sizes, int n_in,
                              void* d_out, int out_size)
{
    const int*   edge_src = (const int*)  d_in[1];
    const int*   edge_dst = (const int*)  d_in[2];
    const float* dist     = (const float*)d_in[3];
    const float* vec      = (const float*)d_in[4];
    const float* pol      = (const float*)d_in[5];
    float* out = (float*)d_out;

    const int E = in_sizes[1];
    const int blocks = (E + TPB - 1) / TPB;
    thole_kernel<<<blocks, TPB>>>(edge_src, edge_dst, dist, vec, pol, out, E);
}